// round 3
// baseline (speedup 1.0000x reference)
#include <cuda_runtime.h>
#include <math.h>

#define QN 16
#define IN 64
#define PB 128
#define JN 256
#define DN 768

// Scratch (device globals: no allocation, allowed by harness rules)
__device__ float g_qn[QN * IN * DN];        // ~3 MB normalized q
__device__ float g_pn[PB * JN * DN];        // ~100 MB normalized p
__device__ float g_scores[QN * PB];
__device__ float g_mv[QN * PB];

// ---------------------------------------------------------------------------
// Row L2-normalize: one block per row of 768, 256 threads
// ---------------------------------------------------------------------------
__device__ __forceinline__ void normalize_row(const float* __restrict__ xr,
                                              float* __restrict__ yr) {
    int tid = threadIdx.x;
    float v0 = xr[tid], v1 = xr[tid + 256], v2 = xr[tid + 512];
    float ss = v0 * v0 + v1 * v1 + v2 * v2;
#pragma unroll
    for (int o = 16; o; o >>= 1) ss += __shfl_xor_sync(0xffffffffu, ss, o);
    __shared__ float red[8];
    __shared__ float inv;
    if ((tid & 31) == 0) red[tid >> 5] = ss;
    __syncthreads();
    if (tid == 0) {
        float t = 0.f;
#pragma unroll
        for (int i = 0; i < 8; i++) t += red[i];
        float n = sqrtf(t);
        inv = 1.0f / fmaxf(n, 1e-12f);
    }
    __syncthreads();
    float iv = inv;
    yr[tid] = v0 * iv;
    yr[tid + 256] = v1 * iv;
    yr[tid + 512] = v2 * iv;
}

__global__ void norm_q_kernel(const float* __restrict__ x) {
    size_t row = blockIdx.x;
    normalize_row(x + row * DN, g_qn + row * DN);
}

__global__ void norm_p_kernel(const float* __restrict__ x) {
    size_t row = blockIdx.x;
    normalize_row(x + row * DN, g_pn + row * DN);
}

// ---------------------------------------------------------------------------
// scores[q][p] = dot(q_hidden[q,0,:], p_hidden[p,0,:])
// ---------------------------------------------------------------------------
__global__ void scores_kernel(const float* __restrict__ qh,
                              const float* __restrict__ ph) {
    int q = blockIdx.x;
    int p = threadIdx.x;  // 128 threads
    __shared__ float qs[DN];
    for (int k = p; k < DN; k += PB) qs[k] = qh[(size_t)q * IN * DN + k];
    __syncthreads();
    const float* pr = ph + (size_t)p * JN * DN;  // row j=0 of page p
    float s = 0.f;
    for (int k = 0; k < DN; k++) s = fmaf(qs[k], pr[k], s);
    g_scores[q * PB + p] = s;
}

// ---------------------------------------------------------------------------
// mv_scores[q][p] = max_{i,j} qn[q,i,:] . pn[p,j,:]
// Register-blocked GEMM tile 64(i) x 256(j), K=768, 8x8 microtile per thread.
// ---------------------------------------------------------------------------
__global__ __launch_bounds__(256) void mv_kernel() {
    const int p = blockIdx.x;
    const int q = blockIdx.y;
    __shared__ float As[32][68];    // [k][i], padded (stride%4==0 for float4)
    __shared__ float Bs[32][260];   // [k][j], padded

    const float* Aq = g_qn + (size_t)q * IN * DN;
    const float* Bp = g_pn + (size_t)p * JN * DN;
    const int tid = threadIdx.x;
    const int ti = tid >> 5;   // warp id -> i block (8 rows)
    const int tj = tid & 31;   // lane -> j block (8 cols)

    float acc[8][8];
#pragma unroll
    for (int u = 0; u < 8; u++)
#pragma unroll
        for (int v = 0; v < 8; v++) acc[u][v] = 0.f;

    for (int k0 = 0; k0 < DN; k0 += 32) {
        // A chunk: 64 rows x 32 k = 512 float4, 2 per thread (transpose store)
#pragma unroll
        for (int r = 0; r < 2; r++) {
            int idx = tid * 2 + r;
            int i = idx >> 3;
            int kq = (idx & 7) << 2;
            float4 v = *(const float4*)(Aq + (size_t)i * DN + k0 + kq);
            As[kq + 0][i] = v.x;
            As[kq + 1][i] = v.y;
            As[kq + 2][i] = v.z;
            As[kq + 3][i] = v.w;
        }
        // B chunk: 256 rows x 32 k = 2048 float4, 8 per thread
#pragma unroll
        for (int r = 0; r < 8; r++) {
            int idx = tid + 256 * r;
            int j = idx >> 3;
            int kq = (idx & 7) << 2;
            float4 v = *(const float4*)(Bp + (size_t)j * DN + k0 + kq);
            Bs[kq + 0][j] = v.x;
            Bs[kq + 1][j] = v.y;
            Bs[kq + 2][j] = v.z;
            Bs[kq + 3][j] = v.w;
        }
        __syncthreads();

#pragma unroll 4
        for (int k = 0; k < 32; k++) {
            float a[8], b[8];
            const float4* ap = (const float4*)(&As[k][ti * 8]);
            ((float4*)a)[0] = ap[0];
            ((float4*)a)[1] = ap[1];
            const float4* bq = (const float4*)(&Bs[k][tj * 8]);
            ((float4*)b)[0] = bq[0];
            ((float4*)b)[1] = bq[1];
#pragma unroll
            for (int u = 0; u < 8; u++)
#pragma unroll
                for (int v = 0; v < 8; v++)
                    acc[u][v] = fmaf(a[u], b[v], acc[u][v]);
        }
        __syncthreads();
    }

    float mx = -INFINITY;
#pragma unroll
    for (int u = 0; u < 8; u++)
#pragma unroll
        for (int v = 0; v < 8; v++) mx = fmaxf(mx, acc[u][v]);
#pragma unroll
    for (int o = 16; o; o >>= 1) mx = fmaxf(mx, __shfl_xor_sync(0xffffffffu, mx, o));
    __shared__ float wred[8];
    if (tj == 0) wred[ti] = mx;
    __syncthreads();
    if (tid == 0) {
        float r = wred[0];
#pragma unroll
        for (int i = 1; i < 8; i++) r = fmaxf(r, wred[i]);
        g_mv[q * PB + p] = r;
    }
}

// ---------------------------------------------------------------------------
// Final loss: 16 warps, one per q-row of 128 entries (4 per lane).
// NOTE: reference overwrites loss_mulvec1 with the KLD term; CE(mv) is dead.
// ---------------------------------------------------------------------------
__global__ void loss_kernel(float* __restrict__ out) {
    int tid = threadIdx.x;  // 512
    int w = tid >> 5;       // q row
    int lane = tid & 31;
    const float* sr = g_scores + w * PB;
    const float* mr = g_mv + w * PB;
    float s[4], m[4], si[4];
#pragma unroll
    for (int c = 0; c < 4; c++) {
        int j = lane + 32 * c;
        s[c] = sr[j];
        m[c] = mr[j];
        si[c] = s[c] + 0.3f * m[c];  // W1=1.0, W3=0.3, TEMPERATURE=1.0
    }
    float mxs = -INFINITY, mxm = -INFINITY, mxi = -INFINITY;
#pragma unroll
    for (int c = 0; c < 4; c++) {
        mxs = fmaxf(mxs, s[c]);
        mxm = fmaxf(mxm, m[c]);
        mxi = fmaxf(mxi, si[c]);
    }
#pragma unroll
    for (int o = 16; o; o >>= 1) {
        mxs = fmaxf(mxs, __shfl_xor_sync(0xffffffffu, mxs, o));
        mxm = fmaxf(mxm, __shfl_xor_sync(0xffffffffu, mxm, o));
        mxi = fmaxf(mxi, __shfl_xor_sync(0xffffffffu, mxi, o));
    }
    float es = 0.f, em = 0.f, ei = 0.f;
#pragma unroll
    for (int c = 0; c < 4; c++) {
        es += expf(s[c] - mxs);
        em += expf(m[c] - mxm);
        ei += expf(si[c] - mxi);
    }
#pragma unroll
    for (int o = 16; o; o >>= 1) {
        es += __shfl_xor_sync(0xffffffffu, es, o);
        em += __shfl_xor_sync(0xffffffffu, em, o);
        ei += __shfl_xor_sync(0xffffffffu, ei, o);
    }
    float lse_s = mxs + logf(es);
    float lse_m = mxm + logf(em);
    float lse_i = mxi + logf(ei);

    // KLD terms: target = log_softmax(s_inter), inputs = log_softmax(scores/mv)
    float k1 = 0.f, k2 = 0.f;
#pragma unroll
    for (int c = 0; c < 4; c++) {
        float t = si[c] - lse_i;
        float pb = expf(t);
        k1 += pb * (t - (s[c] - lse_s));
        k2 += pb * (t - (m[c] - lse_m));
    }
#pragma unroll
    for (int o = 16; o; o >>= 1) {
        k1 += __shfl_xor_sync(0xffffffffu, k1, o);
        k2 += __shfl_xor_sync(0xffffffffu, k2, o);
    }

    __shared__ float sm[16][4];
    if (lane == 0) {
        int tgt = w * 8;  // group_size = 128/16
        float ce_s = lse_s - sr[tgt];
        float ce_i = lse_i - (sr[tgt] + 0.3f * mr[tgt]);
        sm[w][0] = ce_s;
        sm[w][1] = ce_i;
        sm[w][2] = k1;
        sm[w][3] = k2;
    }
    __syncthreads();
    if (tid == 0) {
        float ce_s = 0.f, ce_i = 0.f, k1s = 0.f, k2s = 0.f;
#pragma unroll
        for (int i = 0; i < 16; i++) {
            ce_s += sm[i][0];
            ce_i += sm[i][1];
            k1s += sm[i][2];
            k2s += sm[i][3];
        }
        ce_s *= (1.0f / 16.0f);
        ce_i *= (1.0f / 16.0f);
        k1s *= (1.0f / 16.0f);
        k2s *= (1.0f / 16.0f);
        // loss_dense1=ce_s, loss_inter=ce_i, loss_dense2=k1s, loss_mulvec1=k2s
        float L1 = 0.3f * (ce_s + k2s + ce_i);
        float L2 = 0.2f * (k1s + k2s);
        out[0] = 0.5f * (L1 + L2);
    }
}

// ---------------------------------------------------------------------------
extern "C" void kernel_launch(void* const* d_in, const int* in_sizes, int n_in,
                              void* d_out, int out_size) {
    const float* qh = (const float*)d_in[0];
    const float* ph = (const float*)d_in[1];
    // Defensive: q_hidden has 16*64*768 = 786432 elems, p_hidden 25165824.
    if (n_in >= 2 && in_sizes[0] > in_sizes[1]) {
        const float* t = qh; qh = ph; ph = t;
    }

    norm_q_kernel<<<QN * IN, 256>>>(qh);
    norm_p_kernel<<<PB * JN, 256>>>(ph);
    scores_kernel<<<QN, PB>>>(qh, ph);
    mv_kernel<<<dim3(PB, QN), 256>>>();
    loss_kernel<<<1, 512>>>((float*)d_out);
}

// round 5
// speedup vs baseline: 3.6992x; 3.6992x over previous
#include <cuda_runtime.h>
#include <cstdint>
#include <math.h>

#define QN 16
#define IN 64
#define PB 128
#define JN 256
#define DN 768

#define NSLAB 24               // 768 / 32
#define STAGE_BYTES 49152      // A 128x128B (16KB) + B 256x128B (32KB)
#define NSTAGE 3
#define DYN_SMEM (NSTAGE * STAGE_BYTES + 256)

// Scratch (device globals: no allocation)
__device__ float g_invq[QN * IN];
__device__ float g_invp[PB * JN];
__device__ float g_scores[QN * PB];
__device__ float g_mv[QN * PB];

// ---------------------------------------------------------------------------
// Helpers
// ---------------------------------------------------------------------------
static __device__ __forceinline__ uint32_t smem_u32(const void* p) {
    uint32_t a;
    asm("{ .reg .u64 t; cvta.to.shared.u64 t, %1; cvt.u32.u64 %0, t; }"
        : "=r"(a) : "l"(p));
    return a;
}

#define SWZ(o) ((o) ^ (((o) >> 3) & 0x70))

static __device__ __forceinline__ void cpasync16(uint32_t saddr, const void* g) {
    asm volatile("cp.async.cg.shared.global [%0], [%1], 16;" :: "r"(saddr), "l"(g) : "memory");
}

static __device__ __forceinline__ void mma_tf32(float* c, uint32_t a0, uint32_t a1,
                                                uint32_t a2, uint32_t a3,
                                                uint32_t b0, uint32_t b1) {
    asm volatile(
        "mma.sync.aligned.m16n8k8.row.col.f32.tf32.tf32.f32 "
        "{%0,%1,%2,%3}, {%4,%5,%6,%7}, {%8,%9}, {%0,%1,%2,%3};"
        : "+f"(c[0]), "+f"(c[1]), "+f"(c[2]), "+f"(c[3])
        : "r"(a0), "r"(a1), "r"(a2), "r"(a3), "r"(b0), "r"(b1));
}

// ---------------------------------------------------------------------------
// Inverse-norm kernels: one block per row of 768
// ---------------------------------------------------------------------------
static __device__ __forceinline__ float row_invnorm(const float* __restrict__ xr) {
    int tid = threadIdx.x;
    float v0 = xr[tid], v1 = xr[tid + 256], v2 = xr[tid + 512];
    float ss = v0 * v0 + v1 * v1 + v2 * v2;
#pragma unroll
    for (int o = 16; o; o >>= 1) ss += __shfl_xor_sync(0xffffffffu, ss, o);
    __shared__ float red[8];
    if ((tid & 31) == 0) red[tid >> 5] = ss;
    __syncthreads();
    float t = 0.f;
#pragma unroll
    for (int i = 0; i < 8; i++) t += red[i];
    return 1.0f / fmaxf(sqrtf(t), 1e-12f);
}

__global__ void invnorm_q_kernel(const float* __restrict__ x) {
    size_t row = blockIdx.x;
    float iv = row_invnorm(x + row * DN);
    if (threadIdx.x == 0) g_invq[row] = iv;
}

__global__ void invnorm_p_kernel(const float* __restrict__ x) {
    size_t row = blockIdx.x;
    float iv = row_invnorm(x + row * DN);
    if (threadIdx.x == 0) g_invp[row] = iv;
}

// ---------------------------------------------------------------------------
// scores[q][p] = dot(q_hidden[q,0,:], p_hidden[p,0,:])   (fp32, tiny)
// ---------------------------------------------------------------------------
__global__ void scores_kernel(const float* __restrict__ qh,
                              const float* __restrict__ ph) {
    int q = blockIdx.x;
    int p = threadIdx.x;  // 128 threads
    __shared__ float qs[DN];
    for (int k = p; k < DN; k += PB) qs[k] = qh[(size_t)q * IN * DN + k];
    __syncthreads();
    const float* pr = ph + (size_t)p * JN * DN;
    float s = 0.f;
    for (int k = 0; k < DN; k++) s = fmaf(qs[k], pr[k], s);
    g_scores[q * PB + p] = s;
}

// ---------------------------------------------------------------------------
// mv GEMM via legacy tf32 mma.sync (m16n8k8).
// Grid: (p=128, mb=8). CTA tile: 128 rows (i) x 256 cols (j), K=768 in 24
// slabs of 32. 8 warps = 4(m) x 2(n); warp tile 32x128 = 2 x 16 fragments.
// Epilogue: mv[q][p] = max D[i][j] * invq[i] * invp[j]  (2 q rows per CTA).
// ---------------------------------------------------------------------------
static __device__ __forceinline__ void load_slab(const float* __restrict__ qh,
                                                 const float* __restrict__ ph,
                                                 uint32_t stage_base, int mb, int p,
                                                 int k0, int tid) {
    // A: 128 rows x 32 floats (1024 float4), 4 per thread
#pragma unroll
    for (int i = 0; i < 4; i++) {
        int idx = tid + 256 * i;
        int r = idx >> 3, c = idx & 7;
        const float* g = qh + (size_t)(mb * 128 + r) * DN + k0 + c * 4;
        cpasync16(stage_base + SWZ(r * 128 + c * 16), g);
    }
    // B: 256 rows x 32 floats (2048 float4), 8 per thread
    uint32_t bbase = stage_base + 16384;
#pragma unroll
    for (int i = 0; i < 8; i++) {
        int idx = tid + 256 * i;
        int r = idx >> 3, c = idx & 7;
        const float* g = ph + (size_t)(p * 256 + r) * DN + k0 + c * 4;
        cpasync16(bbase + SWZ(r * 128 + c * 16), g);
    }
}

__global__ __launch_bounds__(256, 1) void mv_tc_kernel(const float* __restrict__ qh,
                                                       const float* __restrict__ ph) {
    extern __shared__ __align__(128) char dynraw[];
    __shared__ float s_invp[256];
    __shared__ float s_wmax[8];

    const int tid = threadIdx.x;
    const int p = blockIdx.x;
    const int mb = blockIdx.y;
    const int w = tid >> 5, lane = tid & 31;
    const int wm = w >> 1, wn = w & 1;
    const int G = lane >> 2, T = lane & 3;

    const uint32_t dynbase = smem_u32(dynraw);
    s_invp[tid] = g_invp[p * 256 + tid];

    float acc[2][16][4];
#pragma unroll
    for (int mt = 0; mt < 2; mt++)
#pragma unroll
        for (int nt = 0; nt < 16; nt++)
#pragma unroll
            for (int c = 0; c < 4; c++) acc[mt][nt][c] = 0.f;

    // Prologue: fill 2 stages
    load_slab(qh, ph, dynbase + 0 * STAGE_BYTES, mb, p, 0, tid);
    asm volatile("cp.async.commit_group;" ::: "memory");
    load_slab(qh, ph, dynbase + 1 * STAGE_BYTES, mb, p, 32, tid);
    asm volatile("cp.async.commit_group;" ::: "memory");

    for (int s = 0; s < NSLAB; s++) {
        if (s + 2 < NSLAB)
            load_slab(qh, ph, dynbase + ((s + 2) % NSTAGE) * STAGE_BYTES, mb, p,
                      (s + 2) * 32, tid);
        asm volatile("cp.async.commit_group;" ::: "memory");
        asm volatile("cp.async.wait_group 2;" ::: "memory");
        __syncthreads();

        const float* As = (const float*)(dynraw + (s % NSTAGE) * STAGE_BYTES);
        const float* Bs = (const float*)(dynraw + (s % NSTAGE) * STAGE_BYTES + 16384);

#pragma unroll
        for (int kk = 0; kk < 4; kk++) {
            // swizzled k-index: float idx = row*32 + (k ^ (G<<2))
            const int kx0 = (kk * 8 + T) ^ (G << 2);
            const int kx1 = (kk * 8 + T + 4) ^ (G << 2);
            uint32_t a[2][4];
#pragma unroll
            for (int mt = 0; mt < 2; mt++) {
                int ib = wm * 32 + mt * 16 + G;
                a[mt][0] = __float_as_uint(As[ib * 32 + kx0]);
                a[mt][1] = __float_as_uint(As[(ib + 8) * 32 + kx0]);
                a[mt][2] = __float_as_uint(As[ib * 32 + kx1]);
                a[mt][3] = __float_as_uint(As[(ib + 8) * 32 + kx1]);
            }
#pragma unroll
            for (int nt = 0; nt < 16; nt++) {
                int jb = wn * 128 + nt * 8 + G;
                uint32_t b0 = __float_as_uint(Bs[jb * 32 + kx0]);
                uint32_t b1 = __float_as_uint(Bs[jb * 32 + kx1]);
                mma_tf32(acc[0][nt], a[0][0], a[0][1], a[0][2], a[0][3], b0, b1);
                mma_tf32(acc[1][nt], a[1][0], a[1][1], a[1][2], a[1][3], b0, b1);
            }
        }
        __syncthreads();
    }

    // Epilogue: scale by invq[i]*invp[j], max-reduce.
    // Fragment rows: c0/c1 -> row G, c2/c3 -> row G+8; cols 2T, 2T+1.
    float mx = -INFINITY;
#pragma unroll
    for (int mt = 0; mt < 2; mt++) {
        float iq0 = g_invq[mb * 128 + wm * 32 + mt * 16 + G];
        float iq1 = g_invq[mb * 128 + wm * 32 + mt * 16 + G + 8];
#pragma unroll
        for (int nt = 0; nt < 16; nt++) {
            float jp0 = s_invp[wn * 128 + nt * 8 + 2 * T];
            float jp1 = s_invp[wn * 128 + nt * 8 + 2 * T + 1];
            mx = fmaxf(mx, acc[mt][nt][0] * iq0 * jp0);
            mx = fmaxf(mx, acc[mt][nt][1] * iq0 * jp1);
            mx = fmaxf(mx, acc[mt][nt][2] * iq1 * jp0);
            mx = fmaxf(mx, acc[mt][nt][3] * iq1 * jp1);
        }
    }
#pragma unroll
    for (int o = 16; o; o >>= 1) mx = fmaxf(mx, __shfl_xor_sync(0xffffffffu, mx, o));
    if (lane == 0) s_wmax[w] = mx;
    __syncthreads();
    if (tid == 0) {
        float m0 = fmaxf(fmaxf(s_wmax[0], s_wmax[1]), fmaxf(s_wmax[2], s_wmax[3]));
        float m1 = fmaxf(fmaxf(s_wmax[4], s_wmax[5]), fmaxf(s_wmax[6], s_wmax[7]));
        g_mv[(mb * 2 + 0) * PB + p] = m0;
        g_mv[(mb * 2 + 1) * PB + p] = m1;
    }
}

// ---------------------------------------------------------------------------
// Final loss (unchanged from passing R3 kernel)
// ---------------------------------------------------------------------------
__global__ void loss_kernel(float* __restrict__ out) {
    int tid = threadIdx.x;  // 512
    int w = tid >> 5;
    int lane = tid & 31;
    const float* sr = g_scores + w * PB;
    const float* mr = g_mv + w * PB;
    float s[4], m[4], si[4];
#pragma unroll
    for (int c = 0; c < 4; c++) {
        int j = lane + 32 * c;
        s[c] = sr[j];
        m[c] = mr[j];
        si[c] = s[c] + 0.3f * m[c];
    }
    float mxs = -INFINITY, mxm = -INFINITY, mxi = -INFINITY;
#pragma unroll
    for (int c = 0; c < 4; c++) {
        mxs = fmaxf(mxs, s[c]);
        mxm = fmaxf(mxm, m[c]);
        mxi = fmaxf(mxi, si[c]);
    }
#pragma unroll
    for (int o = 16; o; o >>= 1) {
        mxs = fmaxf(mxs, __shfl_xor_sync(0xffffffffu, mxs, o));
        mxm = fmaxf(mxm, __shfl_xor_sync(0xffffffffu, mxm, o));
        mxi = fmaxf(mxi, __shfl_xor_sync(0xffffffffu, mxi, o));
    }
    float es = 0.f, em = 0.f, ei = 0.f;
#pragma unroll
    for (int c = 0; c < 4; c++) {
        es += expf(s[c] - mxs);
        em += expf(m[c] - mxm);
        ei += expf(si[c] - mxi);
    }
#pragma unroll
    for (int o = 16; o; o >>= 1) {
        es += __shfl_xor_sync(0xffffffffu, es, o);
        em += __shfl_xor_sync(0xffffffffu, em, o);
        ei += __shfl_xor_sync(0xffffffffu, ei, o);
    }
    float lse_s = mxs + logf(es);
    float lse_m = mxm + logf(em);
    float lse_i = mxi + logf(ei);

    float k1 = 0.f, k2 = 0.f;
#pragma unroll
    for (int c = 0; c < 4; c++) {
        float t = si[c] - lse_i;
        float pb = expf(t);
        k1 += pb * (t - (s[c] - lse_s));
        k2 += pb * (t - (m[c] - lse_m));
    }
#pragma unroll
    for (int o = 16; o; o >>= 1) {
        k1 += __shfl_xor_sync(0xffffffffu, k1, o);
        k2 += __shfl_xor_sync(0xffffffffu, k2, o);
    }

    __shared__ float sm[16][4];
    if (lane == 0) {
        int tgt = w * 8;
        sm[w][0] = lse_s - sr[tgt];
        sm[w][1] = lse_i - (sr[tgt] + 0.3f * mr[tgt]);
        sm[w][2] = k1;
        sm[w][3] = k2;
    }
    __syncthreads();
    if (tid == 0) {
        float ce_s = 0.f, ce_i = 0.f, k1s = 0.f, k2s = 0.f;
#pragma unroll
        for (int i = 0; i < 16; i++) {
            ce_s += sm[i][0];
            ce_i += sm[i][1];
            k1s += sm[i][2];
            k2s += sm[i][3];
        }
        ce_s *= (1.0f / 16.0f);
        ce_i *= (1.0f / 16.0f);
        k1s *= (1.0f / 16.0f);
        k2s *= (1.0f / 16.0f);
        float L1 = 0.3f * (ce_s + k2s + ce_i);
        float L2 = 0.2f * (k1s + k2s);
        out[0] = 0.5f * (L1 + L2);
    }
}

// ---------------------------------------------------------------------------
extern "C" void kernel_launch(void* const* d_in, const int* in_sizes, int n_in,
                              void* d_out, int out_size) {
    const float* qh = (const float*)d_in[0];
    const float* ph = (const float*)d_in[1];
    if (n_in >= 2 && in_sizes[0] > in_sizes[1]) {
        const float* t = qh; qh = ph; ph = t;
    }

    cudaFuncSetAttribute(mv_tc_kernel, cudaFuncAttributeMaxDynamicSharedMemorySize,
                         DYN_SMEM);

    invnorm_q_kernel<<<QN * IN, 256>>>(qh);
    invnorm_p_kernel<<<PB * JN, 256>>>(ph);
    scores_kernel<<<QN, PB>>>(qh, ph);
    mv_tc_kernel<<<dim3(PB, 8), 256, DYN_SMEM>>>(qh, ph);
    loss_kernel<<<1, 512>>>((float*)d_out);
}

// round 6
// speedup vs baseline: 7.7556x; 2.0965x over previous
#include <cuda_runtime.h>
#include <cuda_bf16.h>
#include <cstdint>
#include <math.h>

#define QN 16
#define IN 64
#define PB 128
#define JN 256
#define DN 768

#define NSLAB 12               // 768 / 64 bf16 per slab
#define STAGE_BYTES 49152      // A 128x128B (16KB) + B 256x128B (32KB)
#define NSTAGE 4
#define DYN_SMEM (NSTAGE * STAGE_BYTES + 128)

// Scratch (device globals: no allocation)
__device__ __nv_bfloat16 g_qbf[QN * IN * DN];    // 1.5 MB normalized q, bf16
__device__ __nv_bfloat16 g_pbf[PB * JN * DN];    // 48 MB normalized p, bf16
__device__ float g_scores[QN * PB];
__device__ float g_mv[QN * PB];

// ---------------------------------------------------------------------------
// Helpers
// ---------------------------------------------------------------------------
static __device__ __forceinline__ uint32_t smem_u32(const void* p) {
    uint32_t a;
    asm("{ .reg .u64 t; cvta.to.shared.u64 t, %1; cvt.u32.u64 %0, t; }"
        : "=r"(a) : "l"(p));
    return a;
}

#define SWZ(o) ((o) ^ (((o) >> 3) & 0x70))

static __device__ __forceinline__ void cpasync16(uint32_t saddr, const void* g) {
    asm volatile("cp.async.cg.shared.global [%0], [%1], 16;" :: "r"(saddr), "l"(g) : "memory");
}

static __device__ __forceinline__ void ldmx4(uint32_t* r, uint32_t addr) {
    asm volatile("ldmatrix.sync.aligned.m8n8.x4.shared.b16 {%0,%1,%2,%3}, [%4];"
                 : "=r"(r[0]), "=r"(r[1]), "=r"(r[2]), "=r"(r[3]) : "r"(addr));
}

static __device__ __forceinline__ void mma_bf16(float* c, const uint32_t* a,
                                                uint32_t b0, uint32_t b1) {
    asm volatile(
        "mma.sync.aligned.m16n8k16.row.col.f32.bf16.bf16.f32 "
        "{%0,%1,%2,%3}, {%4,%5,%6,%7}, {%8,%9}, {%0,%1,%2,%3};"
        : "+f"(c[0]), "+f"(c[1]), "+f"(c[2]), "+f"(c[3])
        : "r"(a[0]), "r"(a[1]), "r"(a[2]), "r"(a[3]), "r"(b0), "r"(b1));
}

// ---------------------------------------------------------------------------
// Normalize + convert to bf16: one block (192 threads) per row of 768.
// Thread t owns float4 t -> writes 2 bf16x2 (coalesced 4B stores).
// ---------------------------------------------------------------------------
static __device__ __forceinline__ void norm_convert_row(const float* __restrict__ xr,
                                                        __nv_bfloat162* __restrict__ yr) {
    int t = threadIdx.x;  // 192
    float4 v = ((const float4*)xr)[t];
    float ss = v.x * v.x + v.y * v.y + v.z * v.z + v.w * v.w;
#pragma unroll
    for (int o = 16; o; o >>= 1) ss += __shfl_xor_sync(0xffffffffu, ss, o);
    __shared__ float red[6];
    if ((t & 31) == 0) red[t >> 5] = ss;
    __syncthreads();
    float tot = 0.f;
#pragma unroll
    for (int i = 0; i < 6; i++) tot += red[i];
    float inv = 1.0f / fmaxf(sqrtf(tot), 1e-12f);
    yr[2 * t + 0] = __floats2bfloat162_rn(v.x * inv, v.y * inv);
    yr[2 * t + 1] = __floats2bfloat162_rn(v.z * inv, v.w * inv);
}

__global__ void norm_q_kernel(const float* __restrict__ x) {
    size_t row = blockIdx.x;
    norm_convert_row(x + row * DN, (__nv_bfloat162*)(g_qbf + row * DN));
}

__global__ void norm_p_kernel(const float* __restrict__ x) {
    size_t row = blockIdx.x;
    norm_convert_row(x + row * DN, (__nv_bfloat162*)(g_pbf + row * DN));
}

// ---------------------------------------------------------------------------
// scores[q][p] = dot(q_hidden[q,0,:], p_hidden[p,0,:])  fp32, warp per pair
// grid 128 (p), block 512 (16 warps = 16 q)
// ---------------------------------------------------------------------------
__global__ void scores_kernel(const float* __restrict__ qh,
                              const float* __restrict__ ph) {
    int p = blockIdx.x;
    int q = threadIdx.x >> 5;
    int lane = threadIdx.x & 31;
    const float* qr = qh + (size_t)q * IN * DN;
    const float* pr = ph + (size_t)p * JN * DN;
    float s = 0.f;
#pragma unroll
    for (int i = 0; i < DN / 32; i++) s = fmaf(qr[lane + 32 * i], pr[lane + 32 * i], s);
#pragma unroll
    for (int o = 16; o; o >>= 1) s += __shfl_xor_sync(0xffffffffu, s, o);
    if (lane == 0) g_scores[q * PB + p] = s;
}

// ---------------------------------------------------------------------------
// mv GEMM via bf16 mma.sync m16n8k16 on pre-normalized bf16 data.
// Grid (p=128, mb=8). CTA tile 128(i) x 256(j), K=768 in 12 slabs of 64.
// 8 warps = 4(m) x 2(n); warp tile 32x128 = 2(mt) x 16(nt) fragments.
// ldmatrix x4 feeds; SW128 swizzle; epilogue is a pure max (data pre-scaled).
// ---------------------------------------------------------------------------
static __device__ __forceinline__ void load_slab(uint32_t stage_base, int mb, int p,
                                                 int k0, int tid) {
    // A: 128 rows x 64 bf16 (128B) = 1024 x 16B chunks, 4 per thread
#pragma unroll
    for (int i = 0; i < 4; i++) {
        int idx = tid + 256 * i;
        int r = idx >> 3, c = idx & 7;
        const __nv_bfloat16* g = g_qbf + (size_t)(mb * 128 + r) * DN + k0 + c * 8;
        cpasync16(stage_base + SWZ(r * 128 + c * 16), g);
    }
    // B: 256 rows x 64 bf16 = 2048 x 16B, 8 per thread
    uint32_t bbase = stage_base + 16384;
#pragma unroll
    for (int i = 0; i < 8; i++) {
        int idx = tid + 256 * i;
        int r = idx >> 3, c = idx & 7;
        const __nv_bfloat16* g = g_pbf + (size_t)(p * 256 + r) * DN + k0 + c * 8;
        cpasync16(bbase + SWZ(r * 128 + c * 16), g);
    }
}

__global__ __launch_bounds__(256, 1) void mv_tc_kernel() {
    extern __shared__ __align__(128) char dynraw[];
    __shared__ float s_wmax[8];

    const int tid = threadIdx.x;
    const int p = blockIdx.x;
    const int mb = blockIdx.y;
    const int w = tid >> 5, lane = tid & 31;
    const int wm = w >> 1, wn = w & 1;

    const uint32_t dynbase = smem_u32(dynraw);

    // --- per-lane ldmatrix address components (constant across loop) ---
    // A frag (m16n8k16, ldmatrix x4): sel = lane>>3
    //   m0: rows 0-7 klo | m1: rows 8-15 klo | m2: rows 0-7 khi | m3: rows 8-15 khi
    const int selA = lane >> 3;
    const int arow_l = (lane & 7) + ((selA & 1) << 3);   // row within 16
    const int achunk_h = selA >> 1;                      // 0 = k0-7, 1 = k8-15
    const int arx = lane & 7;                            // swizzle xor (row & 7)
    // aRowOff[mt]: byte offset of this lane's A row
    uint32_t aRowOff[2];
#pragma unroll
    for (int mt = 0; mt < 2; mt++)
        aRowOff[mt] = (uint32_t)(wm * 32 + mt * 16 + arow_l) * 128u;

    // B frag (x4 = two n-tiles): lanes 0-7: j0-7 klo | 8-15: j0-7 khi
    //                            | 16-23: j8-15 klo | 24-31: j8-15 khi
    const int jrow_l = (lane & 7) + ((lane >> 4) << 3);  // row within 16
    const int bchunk_h = (lane >> 3) & 1;
    const int brx = lane & 7;
    const uint32_t bRowOff0 = (uint32_t)(wn * 128 + jrow_l) * 128u;  // + np*16*128

    float acc[2][16][4];
#pragma unroll
    for (int mt = 0; mt < 2; mt++)
#pragma unroll
        for (int nt = 0; nt < 16; nt++)
#pragma unroll
            for (int c = 0; c < 4; c++) acc[mt][nt][c] = 0.f;

    // Prologue: fill 3 stages
#pragma unroll
    for (int pre = 0; pre < 3; pre++) {
        load_slab(dynbase + pre * STAGE_BYTES, mb, p, pre * 64, tid);
        asm volatile("cp.async.commit_group;" ::: "memory");
    }

    for (int s = 0; s < NSLAB; s++) {
        if (s + 3 < NSLAB)
            load_slab(dynbase + ((s + 3) % NSTAGE) * STAGE_BYTES, mb, p,
                      (s + 3) * 64, tid);
        asm volatile("cp.async.commit_group;" ::: "memory");
        asm volatile("cp.async.wait_group 3;" ::: "memory");
        __syncthreads();

        const uint32_t Ab = dynbase + (s % NSTAGE) * STAGE_BYTES;
        const uint32_t Bb = Ab + 16384;

#pragma unroll
        for (int kk = 0; kk < 4; kk++) {           // 4 k16-steps per 64-slab
            const int ca = ((kk * 2 + achunk_h) ^ arx) << 4;
            const int cb = ((kk * 2 + bchunk_h) ^ brx) << 4;
            uint32_t a[2][4];
            ldmx4(a[0], Ab + aRowOff[0] + ca);
            ldmx4(a[1], Ab + aRowOff[1] + ca);
#pragma unroll
            for (int np = 0; np < 8; np++) {
                uint32_t b[4];
                ldmx4(b, Bb + bRowOff0 + (uint32_t)np * 2048u + cb);
                mma_bf16(acc[0][np * 2 + 0], a[0], b[0], b[1]);
                mma_bf16(acc[1][np * 2 + 0], a[1], b[0], b[1]);
                mma_bf16(acc[0][np * 2 + 1], a[0], b[2], b[3]);
                mma_bf16(acc[1][np * 2 + 1], a[1], b[2], b[3]);
            }
        }
        __syncthreads();
    }

    // Epilogue: pure max (operands pre-normalized)
    float mx = -INFINITY;
#pragma unroll
    for (int mt = 0; mt < 2; mt++)
#pragma unroll
        for (int nt = 0; nt < 16; nt++)
#pragma unroll
            for (int c = 0; c < 4; c++) mx = fmaxf(mx, acc[mt][nt][c]);
#pragma unroll
    for (int o = 16; o; o >>= 1) mx = fmaxf(mx, __shfl_xor_sync(0xffffffffu, mx, o));
    if (lane == 0) s_wmax[w] = mx;
    __syncthreads();
    if (tid == 0) {
        float m0 = fmaxf(fmaxf(s_wmax[0], s_wmax[1]), fmaxf(s_wmax[2], s_wmax[3]));
        float m1 = fmaxf(fmaxf(s_wmax[4], s_wmax[5]), fmaxf(s_wmax[6], s_wmax[7]));
        g_mv[(mb * 2 + 0) * PB + p] = m0;
        g_mv[(mb * 2 + 1) * PB + p] = m1;
    }
}

// ---------------------------------------------------------------------------
// Final loss (unchanged logic)
// ---------------------------------------------------------------------------
__global__ void loss_kernel(float* __restrict__ out) {
    int tid = threadIdx.x;  // 512
    int w = tid >> 5;
    int lane = tid & 31;
    const float* sr = g_scores + w * PB;
    const float* mr = g_mv + w * PB;
    float s[4], m[4], si[4];
#pragma unroll
    for (int c = 0; c < 4; c++) {
        int j = lane + 32 * c;
        s[c] = sr[j];
        m[c] = mr[j];
        si[c] = s[c] + 0.3f * m[c];
    }
    float mxs = -INFINITY, mxm = -INFINITY, mxi = -INFINITY;
#pragma unroll
    for (int c = 0; c < 4; c++) {
        mxs = fmaxf(mxs, s[c]);
        mxm = fmaxf(mxm, m[c]);
        mxi = fmaxf(mxi, si[c]);
    }
#pragma unroll
    for (int o = 16; o; o >>= 1) {
        mxs = fmaxf(mxs, __shfl_xor_sync(0xffffffffu, mxs, o));
        mxm = fmaxf(mxm, __shfl_xor_sync(0xffffffffu, mxm, o));
        mxi = fmaxf(mxi, __shfl_xor_sync(0xffffffffu, mxi, o));
    }
    float es = 0.f, em = 0.f, ei = 0.f;
#pragma unroll
    for (int c = 0; c < 4; c++) {
        es += expf(s[c] - mxs);
        em += expf(m[c] - mxm);
        ei += expf(si[c] - mxi);
    }
#pragma unroll
    for (int o = 16; o; o >>= 1) {
        es += __shfl_xor_sync(0xffffffffu, es, o);
        em += __shfl_xor_sync(0xffffffffu, em, o);
        ei += __shfl_xor_sync(0xffffffffu, ei, o);
    }
    float lse_s = mxs + logf(es);
    float lse_m = mxm + logf(em);
    float lse_i = mxi + logf(ei);

    float k1 = 0.f, k2 = 0.f;
#pragma unroll
    for (int c = 0; c < 4; c++) {
        float t = si[c] - lse_i;
        float pb = expf(t);
        k1 += pb * (t - (s[c] - lse_s));
        k2 += pb * (t - (m[c] - lse_m));
    }
#pragma unroll
    for (int o = 16; o; o >>= 1) {
        k1 += __shfl_xor_sync(0xffffffffu, k1, o);
        k2 += __shfl_xor_sync(0xffffffffu, k2, o);
    }

    __shared__ float sm[16][4];
    if (lane == 0) {
        int tgt = w * 8;
        sm[w][0] = lse_s - sr[tgt];
        sm[w][1] = lse_i - (sr[tgt] + 0.3f * mr[tgt]);
        sm[w][2] = k1;
        sm[w][3] = k2;
    }
    __syncthreads();
    if (tid == 0) {
        float ce_s = 0.f, ce_i = 0.f, k1s = 0.f, k2s = 0.f;
#pragma unroll
        for (int i = 0; i < 16; i++) {
            ce_s += sm[i][0];
            ce_i += sm[i][1];
            k1s += sm[i][2];
            k2s += sm[i][3];
        }
        ce_s *= (1.0f / 16.0f);
        ce_i *= (1.0f / 16.0f);
        k1s *= (1.0f / 16.0f);
        k2s *= (1.0f / 16.0f);
        float L1 = 0.3f * (ce_s + k2s + ce_i);
        float L2 = 0.2f * (k1s + k2s);
        out[0] = 0.5f * (L1 + L2);
    }
}

// ---------------------------------------------------------------------------
extern "C" void kernel_launch(void* const* d_in, const int* in_sizes, int n_in,
                              void* d_out, int out_size) {
    const float* qh = (const float*)d_in[0];
    const float* ph = (const float*)d_in[1];
    if (n_in >= 2 && in_sizes[0] > in_sizes[1]) {
        const float* t = qh; qh = ph; ph = t;
    }

    cudaFuncSetAttribute(mv_tc_kernel, cudaFuncAttributeMaxDynamicSharedMemorySize,
                         DYN_SMEM);

    norm_q_kernel<<<QN * IN, 192>>>(qh);
    norm_p_kernel<<<PB * JN, 192>>>(ph);
    scores_kernel<<<PB, 512>>>(qh, ph);
    mv_tc_kernel<<<dim3(PB, 8), 256, DYN_SMEM>>>();
    loss_kernel<<<1, 512>>>((float*)d_out);
}

// round 7
// speedup vs baseline: 8.0771x; 1.0415x over previous
#include <cuda_runtime.h>
#include <cuda_bf16.h>
#include <cstdint>
#include <math.h>

#define QN 16
#define IN 64
#define PB 128
#define JN 256
#define DN 768

#define NSLAB 12               // 768 / 64 bf16 per slab
#define A_STAGE 8192           // 64 rows x 128B
#define B_STAGE 32768          // 256 rows x 128B
#define STAGE_BYTES (A_STAGE + B_STAGE)   // 40960
#define NSTAGE 2
#define DYN_SMEM (NSTAGE * STAGE_BYTES)   // 81920

// Scratch (device globals: no allocation)
__device__ __nv_bfloat16 g_qbf[QN * IN * DN];    // 1.5 MB normalized q, bf16
__device__ __nv_bfloat16 g_pbf[PB * JN * DN];    // 48 MB normalized p, bf16
__device__ float g_scores[QN * PB];
__device__ float g_mv[QN * PB];

// ---------------------------------------------------------------------------
// Helpers
// ---------------------------------------------------------------------------
static __device__ __forceinline__ uint32_t smem_u32(const void* p) {
    uint32_t a;
    asm("{ .reg .u64 t; cvta.to.shared.u64 t, %1; cvt.u32.u64 %0, t; }"
        : "=r"(a) : "l"(p));
    return a;
}

#define SWZ(o) ((o) ^ (((o) >> 3) & 0x70))

static __device__ __forceinline__ void cpasync16(uint32_t saddr, const void* g) {
    asm volatile("cp.async.cg.shared.global [%0], [%1], 16;" :: "r"(saddr), "l"(g) : "memory");
}

static __device__ __forceinline__ void ldmx4(uint32_t* r, uint32_t addr) {
    asm volatile("ldmatrix.sync.aligned.m8n8.x4.shared.b16 {%0,%1,%2,%3}, [%4];"
                 : "=r"(r[0]), "=r"(r[1]), "=r"(r[2]), "=r"(r[3]) : "r"(addr));
}

static __device__ __forceinline__ void mma_bf16(float* c, const uint32_t* a,
                                                uint32_t b0, uint32_t b1) {
    asm volatile(
        "mma.sync.aligned.m16n8k16.row.col.f32.bf16.bf16.f32 "
        "{%0,%1,%2,%3}, {%4,%5,%6,%7}, {%8,%9}, {%0,%1,%2,%3};"
        : "+f"(c[0]), "+f"(c[1]), "+f"(c[2]), "+f"(c[3])
        : "r"(a[0]), "r"(a[1]), "r"(a[2]), "r"(a[3]), "r"(b0), "r"(b1));
}

// ---------------------------------------------------------------------------
// Normalize + convert to bf16: one block (192 threads) per row of 768.
// ---------------------------------------------------------------------------
static __device__ __forceinline__ void norm_convert_row(const float* __restrict__ xr,
                                                        __nv_bfloat162* __restrict__ yr) {
    int t = threadIdx.x;  // 192
    float4 v = ((const float4*)xr)[t];
    float ss = v.x * v.x + v.y * v.y + v.z * v.z + v.w * v.w;
#pragma unroll
    for (int o = 16; o; o >>= 1) ss += __shfl_xor_sync(0xffffffffu, ss, o);
    __shared__ float red[6];
    if ((t & 31) == 0) red[t >> 5] = ss;
    __syncthreads();
    float tot = 0.f;
#pragma unroll
    for (int i = 0; i < 6; i++) tot += red[i];
    float inv = 1.0f / fmaxf(sqrtf(tot), 1e-12f);
    yr[2 * t + 0] = __floats2bfloat162_rn(v.x * inv, v.y * inv);
    yr[2 * t + 1] = __floats2bfloat162_rn(v.z * inv, v.w * inv);
}

__global__ void norm_q_kernel(const float* __restrict__ x) {
    size_t row = blockIdx.x;
    norm_convert_row(x + row * DN, (__nv_bfloat162*)(g_qbf + row * DN));
}

__global__ void norm_p_kernel(const float* __restrict__ x) {
    size_t row = blockIdx.x;
    norm_convert_row(x + row * DN, (__nv_bfloat162*)(g_pbf + row * DN));
}

// ---------------------------------------------------------------------------
// scores[q][p] = dot(q_hidden[q,0,:], p_hidden[p,0,:])  fp32, warp per pair
// ---------------------------------------------------------------------------
__global__ void scores_kernel(const float* __restrict__ qh,
                              const float* __restrict__ ph) {
    int p = blockIdx.x;
    int q = threadIdx.x >> 5;
    int lane = threadIdx.x & 31;
    const float* qr = qh + (size_t)q * IN * DN;
    const float* pr = ph + (size_t)p * JN * DN;
    float s = 0.f;
#pragma unroll
    for (int i = 0; i < DN / 32; i++) s = fmaf(qr[lane + 32 * i], pr[lane + 32 * i], s);
#pragma unroll
    for (int o = 16; o; o >>= 1) s += __shfl_xor_sync(0xffffffffu, s, o);
    if (lane == 0) g_scores[q * PB + p] = s;
}

// ---------------------------------------------------------------------------
// mv GEMM via bf16 mma.sync m16n8k16 on pre-normalized bf16 data.
// Grid (p=128, q=16). CTA tile 64(i) x 256(j), K=768 in 12 slabs of 64.
// 8 warps = 2(m) x 4(n); warp tile 32x64 = 2(mt) x 8(nt) fragments.
// 2-stage cp.async pipeline, 2 CTAs/SM.
// ---------------------------------------------------------------------------
static __device__ __forceinline__ void load_slab(uint32_t stage_base, int mb, int p,
                                                 int k0, int tid) {
    // A: 64 rows x 64 bf16 (128B) = 512 x 16B chunks, 2 per thread
#pragma unroll
    for (int i = 0; i < 2; i++) {
        int idx = tid + 256 * i;
        int r = idx >> 3, c = idx & 7;
        const __nv_bfloat16* g = g_qbf + (size_t)(mb * 64 + r) * DN + k0 + c * 8;
        cpasync16(stage_base + SWZ(r * 128 + c * 16), g);
    }
    // B: 256 rows x 64 bf16 = 2048 x 16B, 8 per thread
    uint32_t bbase = stage_base + A_STAGE;
#pragma unroll
    for (int i = 0; i < 8; i++) {
        int idx = tid + 256 * i;
        int r = idx >> 3, c = idx & 7;
        const __nv_bfloat16* g = g_pbf + (size_t)(p * 256 + r) * DN + k0 + c * 8;
        cpasync16(bbase + SWZ(r * 128 + c * 16), g);
    }
}

__global__ __launch_bounds__(256, 2) void mv_tc_kernel() {
    extern __shared__ __align__(128) char dynraw[];
    __shared__ float s_wmax[8];

    const int tid = threadIdx.x;
    const int p = blockIdx.x;
    const int mb = blockIdx.y;  // q row (64 i's per q)
    const int w = tid >> 5, lane = tid & 31;
    const int wm = w >> 2, wn = w & 3;

    const uint32_t dynbase = smem_u32(dynraw);

    // A frag ldmatrix lane mapping (m16n8k16 x4)
    const int selA = lane >> 3;
    const int arow_l = (lane & 7) + ((selA & 1) << 3);
    const int achunk_h = selA >> 1;
    const int arx = lane & 7;
    uint32_t aRowOff[2];
#pragma unroll
    for (int mt = 0; mt < 2; mt++)
        aRowOff[mt] = (uint32_t)(wm * 32 + mt * 16 + arow_l) * 128u;

    // B frag mapping (x4 = two n8 tiles)
    const int jrow_l = (lane & 7) + ((lane >> 4) << 3);
    const int bchunk_h = (lane >> 3) & 1;
    const int brx = lane & 7;
    const uint32_t bRowOff0 = (uint32_t)(wn * 64 + jrow_l) * 128u;  // + np*16*128

    float acc[2][8][4];
#pragma unroll
    for (int mt = 0; mt < 2; mt++)
#pragma unroll
        for (int nt = 0; nt < 8; nt++)
#pragma unroll
            for (int c = 0; c < 4; c++) acc[mt][nt][c] = 0.f;

    // Prologue: fill both stages
    load_slab(dynbase + 0 * STAGE_BYTES, mb, p, 0, tid);
    asm volatile("cp.async.commit_group;" ::: "memory");
    load_slab(dynbase + 1 * STAGE_BYTES, mb, p, 64, tid);
    asm volatile("cp.async.commit_group;" ::: "memory");

    for (int s = 0; s < NSLAB; s++) {
        asm volatile("cp.async.wait_group 1;" ::: "memory");
        __syncthreads();

        const uint32_t Ab = dynbase + (s & 1) * STAGE_BYTES;
        const uint32_t Bb = Ab + A_STAGE;

#pragma unroll
        for (int kk = 0; kk < 4; kk++) {
            const int ca = ((kk * 2 + achunk_h) ^ arx) << 4;
            const int cb = ((kk * 2 + bchunk_h) ^ brx) << 4;
            uint32_t a[2][4];
            ldmx4(a[0], Ab + aRowOff[0] + ca);
            ldmx4(a[1], Ab + aRowOff[1] + ca);
#pragma unroll
            for (int np = 0; np < 4; np++) {
                uint32_t b[4];
                ldmx4(b, Bb + bRowOff0 + (uint32_t)np * 2048u + cb);
                mma_bf16(acc[0][np * 2 + 0], a[0], b[0], b[1]);
                mma_bf16(acc[1][np * 2 + 0], a[1], b[0], b[1]);
                mma_bf16(acc[0][np * 2 + 1], a[0], b[2], b[3]);
                mma_bf16(acc[1][np * 2 + 1], a[1], b[2], b[3]);
            }
        }
        __syncthreads();

        if (s + 2 < NSLAB) {
            load_slab(dynbase + (s & 1) * STAGE_BYTES, mb, p, (s + 2) * 64, tid);
            asm volatile("cp.async.commit_group;" ::: "memory");
        }
    }

    // Epilogue: pure max (operands pre-normalized)
    float mx = -INFINITY;
#pragma unroll
    for (int mt = 0; mt < 2; mt++)
#pragma unroll
        for (int nt = 0; nt < 8; nt++)
#pragma unroll
            for (int c = 0; c < 4; c++) mx = fmaxf(mx, acc[mt][nt][c]);
#pragma unroll
    for (int o = 16; o; o >>= 1) mx = fmaxf(mx, __shfl_xor_sync(0xffffffffu, mx, o));
    if (lane == 0) s_wmax[w] = mx;
    __syncthreads();
    if (tid == 0) {
        float m = s_wmax[0];
#pragma unroll
        for (int i = 1; i < 8; i++) m = fmaxf(m, s_wmax[i]);
        g_mv[mb * PB + p] = m;
    }
}

// ---------------------------------------------------------------------------
// Final loss (unchanged logic)
// ---------------------------------------------------------------------------
__global__ void loss_kernel(float* __restrict__ out) {
    int tid = threadIdx.x;  // 512
    int w = tid >> 5;
    int lane = tid & 31;
    const float* sr = g_scores + w * PB;
    const float* mr = g_mv + w * PB;
    float s[4], m[4], si[4];
#pragma unroll
    for (int c = 0; c < 4; c++) {
        int j = lane + 32 * c;
        s[c] = sr[j];
        m[c] = mr[j];
        si[c] = s[c] + 0.3f * m[c];
    }
    float mxs = -INFINITY, mxm = -INFINITY, mxi = -INFINITY;
#pragma unroll
    for (int c = 0; c < 4; c++) {
        mxs = fmaxf(mxs, s[c]);
        mxm = fmaxf(mxm, m[c]);
        mxi = fmaxf(mxi, si[c]);
    }
#pragma unroll
    for (int o = 16; o; o >>= 1) {
        mxs = fmaxf(mxs, __shfl_xor_sync(0xffffffffu, mxs, o));
        mxm = fmaxf(mxm, __shfl_xor_sync(0xffffffffu, mxm, o));
        mxi = fmaxf(mxi, __shfl_xor_sync(0xffffffffu, mxi, o));
    }
    float es = 0.f, em = 0.f, ei = 0.f;
#pragma unroll
    for (int c = 0; c < 4; c++) {
        es += expf(s[c] - mxs);
        em += expf(m[c] - mxm);
        ei += expf(si[c] - mxi);
    }
#pragma unroll
    for (int o = 16; o; o >>= 1) {
        es += __shfl_xor_sync(0xffffffffu, es, o);
        em += __shfl_xor_sync(0xffffffffu, em, o);
        ei += __shfl_xor_sync(0xffffffffu, ei, o);
    }
    float lse_s = mxs + logf(es);
    float lse_m = mxm + logf(em);
    float lse_i = mxi + logf(ei);

    float k1 = 0.f, k2 = 0.f;
#pragma unroll
    for (int c = 0; c < 4; c++) {
        float t = si[c] - lse_i;
        float pb = expf(t);
        k1 += pb * (t - (s[c] - lse_s));
        k2 += pb * (t - (m[c] - lse_m));
    }
#pragma unroll
    for (int o = 16; o; o >>= 1) {
        k1 += __shfl_xor_sync(0xffffffffu, k1, o);
        k2 += __shfl_xor_sync(0xffffffffu, k2, o);
    }

    __shared__ float sm[16][4];
    if (lane == 0) {
        int tgt = w * 8;
        sm[w][0] = lse_s - sr[tgt];
        sm[w][1] = lse_i - (sr[tgt] + 0.3f * mr[tgt]);
        sm[w][2] = k1;
        sm[w][3] = k2;
    }
    __syncthreads();
    if (tid == 0) {
        float ce_s = 0.f, ce_i = 0.f, k1s = 0.f, k2s = 0.f;
#pragma unroll
        for (int i = 0; i < 16; i++) {
            ce_s += sm[i][0];
            ce_i += sm[i][1];
            k1s += sm[i][2];
            k2s += sm[i][3];
        }
        ce_s *= (1.0f / 16.0f);
        ce_i *= (1.0f / 16.0f);
        k1s *= (1.0f / 16.0f);
        k2s *= (1.0f / 16.0f);
        float L1 = 0.3f * (ce_s + k2s + ce_i);
        float L2 = 0.2f * (k1s + k2s);
        out[0] = 0.5f * (L1 + L2);
    }
}

// ---------------------------------------------------------------------------
extern "C" void kernel_launch(void* const* d_in, const int* in_sizes, int n_in,
                              void* d_out, int out_size) {
    const float* qh = (const float*)d_in[0];
    const float* ph = (const float*)d_in[1];
    if (n_in >= 2 && in_sizes[0] > in_sizes[1]) {
        const float* t = qh; qh = ph; ph = t;
    }

    cudaFuncSetAttribute(mv_tc_kernel, cudaFuncAttributeMaxDynamicSharedMemorySize,
                         DYN_SMEM);

    norm_q_kernel<<<QN * IN, 192>>>(qh);
    norm_p_kernel<<<PB * JN, 192>>>(ph);
    scores_kernel<<<PB, 512>>>(qh, ph);
    mv_tc_kernel<<<dim3(PB, QN), 256, DYN_SMEM>>>();
    loss_kernel<<<1, 512>>>((float*)d_out);
}